// round 2
// baseline (speedup 1.0000x reference)
#include <cuda_runtime.h>
#include <cuda_bf16.h>
#include <cstdint>

// ============================================================
// Problem constants
// ============================================================
#define MTOT 4096
#define NTOT 8192
#define KTOT 2048
#define NG   16
#define GSZ  (NTOT / NG)   // 512

// GEMM tiling
#define BM 128
#define BN 256
#define BK 32                    // bf16 K elements per stage
#define NCHUNK (KTOT / BK)       // 64
#define NSTAGE 3

// Padded smem row stride: 32 bf16 = 64B data, padded to 80B (5x16B slots;
// 5 coprime with 8 -> conflict-free ldmatrix/cp.async without swizzle)
#define ROWB 80

#define SOFF_AH 0
#define SOFF_AL (SOFF_AH + BM * ROWB)          // 10240
#define SOFF_BH (SOFF_AL + BM * ROWB)          // 20480
#define SOFF_BL (SOFF_BH + BN * ROWB)          // 40960
#define STAGE_BYTES (SOFF_BL + BN * ROWB)      // 61440
#define SMEM_TOTAL (NSTAGE * STAGE_BYTES)      // 184320

// ============================================================
// Global scratch (static __device__ allowed; no cudaMalloc)
// ============================================================
__device__ float g_y[(size_t)MTOT * NTOT];                       // 128 MB
__device__ __nv_bfloat16 g_Ah[(size_t)MTOT * KTOT];              // 16 MB
__device__ __nv_bfloat16 g_Al[(size_t)MTOT * KTOT];              // 16 MB
__device__ __nv_bfloat16 g_Bh[(size_t)NTOT * KTOT];              // 32 MB
__device__ __nv_bfloat16 g_Bl[(size_t)NTOT * KTOT];              // 32 MB

// ============================================================
// Helpers
// ============================================================
static __device__ __forceinline__ uint32_t smem_u32(const void* p) {
    uint32_t a;
    asm("{ .reg .u64 t; cvta.to.shared.u64 t, %1; cvt.u32.u64 %0, t; }" : "=r"(a) : "l"(p));
    return a;
}

static __device__ __forceinline__ void cpasync16(uint32_t dst, const void* src) {
    asm volatile("cp.async.cg.shared.global [%0], [%1], 16;" :: "r"(dst), "l"(src) : "memory");
}
#define CP_COMMIT() asm volatile("cp.async.commit_group;" ::: "memory")
#define CP_WAIT1()  asm volatile("cp.async.wait_group 1;" ::: "memory")

static __device__ __forceinline__ void ldsm4(uint32_t addr, uint32_t* r) {
    asm volatile("ldmatrix.sync.aligned.m8n8.x4.shared.b16 {%0,%1,%2,%3}, [%4];"
                 : "=r"(r[0]), "=r"(r[1]), "=r"(r[2]), "=r"(r[3]) : "r"(addr));
}

static __device__ __forceinline__ void mma16816(float* c, const uint32_t* a, const uint32_t* b) {
    asm volatile(
        "mma.sync.aligned.m16n8k16.row.col.f32.bf16.bf16.f32 "
        "{%0,%1,%2,%3}, {%4,%5,%6,%7}, {%8,%9}, {%0,%1,%2,%3};"
        : "+f"(c[0]), "+f"(c[1]), "+f"(c[2]), "+f"(c[3])
        : "r"(a[0]), "r"(a[1]), "r"(a[2]), "r"(a[3]), "r"(b[0]), "r"(b[1]));
}

// ============================================================
// Conversion kernel: fp32 -> bf16 hi + bf16 lo (2-term split)
// ============================================================
__global__ void __launch_bounds__(256)
convert_split_19688130085476(const float* __restrict__ src,
                             __nv_bfloat16* __restrict__ dh,
                             __nv_bfloat16* __restrict__ dl,
                             int n4)
{
    int i = blockIdx.x * blockDim.x + threadIdx.x;
    if (i >= n4) return;
    float4 v = ((const float4*)src)[i];
    float f[4] = {v.x, v.y, v.z, v.w};
    ushort4 hh, ll;
    unsigned short* hp = &hh.x;
    unsigned short* lp = &ll.x;
    #pragma unroll
    for (int j = 0; j < 4; j++) {
        __nv_bfloat16 h = __float2bfloat16(f[j]);
        __nv_bfloat16 l = __float2bfloat16(f[j] - __bfloat162float(h));
        hp[j] = __bfloat16_as_ushort(h);
        lp[j] = __bfloat16_as_ushort(l);
    }
    ((ushort4*)dh)[i] = hh;
    ((ushort4*)dl)[i] = ll;
}

// ============================================================
// GEMM kernel: y = x @ W^T  via 3-term bf16-split HMMA
//   grid (NTOT/BN, MTOT/BM) = (32, 32), 256 threads
// ============================================================
__global__ void __launch_bounds__(256)
gemm_hmma_19688130085476()
{
    extern __shared__ __align__(128) char smem[];
    const uint32_t sbase = smem_u32(smem);
    const int tid = threadIdx.x;
    const int wid = tid >> 5;
    const int lid = tid & 31;

    const int n0 = blockIdx.x * BN;
    const int m0 = blockIdx.y * BM;

    const int warp_m = wid >> 2;   // 0..1 -> 64-row slab
    const int warp_n = wid & 3;    // 0..3 -> 64-col slab

    // ldmatrix lane address components (derived from m8n8.x4 matrix ordering)
    const int a_row_lane   = (lid & 7) + (((lid >> 3) & 1) << 3);
    const int a_chunk_lane = (lid >> 4) & 1;
    const int b_row_lane   = (lid & 7) + (((lid >> 4) & 1) << 3);
    const int b_chunk_lane = (lid >> 3) & 1;

    float acc[4][8][4];
    #pragma unroll
    for (int i = 0; i < 4; i++)
        #pragma unroll
        for (int j = 0; j < 8; j++)
            #pragma unroll
            for (int e = 0; e < 4; e++) acc[i][j][e] = 0.0f;

    // ---- stage loader ----
    auto load_stage = [&](int kc, int slot) {
        const uint32_t sb = sbase + slot * STAGE_BYTES;
        const int k0 = kc * BK;
        #pragma unroll
        for (int i = tid; i < BM * 4; i += 256) {
            int r = i >> 2, c = i & 3;
            size_t g = (size_t)(m0 + r) * KTOT + k0 + c * 8;
            uint32_t d = sb + r * ROWB + c * 16;
            cpasync16(d + SOFF_AH, g_Ah + g);
            cpasync16(d + SOFF_AL, g_Al + g);
        }
        #pragma unroll
        for (int i = tid; i < BN * 4; i += 256) {
            int r = i >> 2, c = i & 3;
            size_t g = (size_t)(n0 + r) * KTOT + k0 + c * 8;
            uint32_t d = sb + r * ROWB + c * 16;
            cpasync16(d + SOFF_BH, g_Bh + g);
            cpasync16(d + SOFF_BL, g_Bl + g);
        }
    };

    // prologue: stages 0 and 1
    load_stage(0, 0); CP_COMMIT();
    load_stage(1, 1); CP_COMMIT();

    for (int kc = 0; kc < NCHUNK; kc++) {
        CP_WAIT1();
        __syncthreads();

        // prefetch stage kc+2 (buffer (kc+2)%3 was consumed at iter kc-1)
        if (kc + 2 < NCHUNK) load_stage(kc + 2, (kc + 2) % NSTAGE);
        CP_COMMIT();

        // ---- compute stage kc ----
        const uint32_t sb = sbase + (kc % NSTAGE) * STAGE_BYTES;
        #pragma unroll
        for (int ks = 0; ks < 2; ks++) {
            uint32_t Ah[4][4], Al[4][4], Bx[4][4];
            const int a_chunk = 2 * ks + a_chunk_lane;
            const int b_chunk = 2 * ks + b_chunk_lane;

            #pragma unroll
            for (int tm = 0; tm < 4; tm++) {
                uint32_t row = warp_m * 64 + tm * 16 + a_row_lane;
                uint32_t ad = sb + row * ROWB + a_chunk * 16;
                ldsm4(ad + SOFF_AH, Ah[tm]);
                ldsm4(ad + SOFF_AL, Al[tm]);
            }
            #pragma unroll
            for (int tn = 0; tn < 4; tn++) {
                uint32_t row = warp_n * 64 + tn * 16 + b_row_lane;
                ldsm4(sb + SOFF_BH + row * ROWB + b_chunk * 16, Bx[tn]);
            }
            // terms Ah*Bh and Al*Bh
            #pragma unroll
            for (int tm = 0; tm < 4; tm++)
                #pragma unroll
                for (int tn = 0; tn < 4; tn++) {
                    mma16816(acc[tm][2 * tn],     Ah[tm], &Bx[tn][0]);
                    mma16816(acc[tm][2 * tn + 1], Ah[tm], &Bx[tn][2]);
                    mma16816(acc[tm][2 * tn],     Al[tm], &Bx[tn][0]);
                    mma16816(acc[tm][2 * tn + 1], Al[tm], &Bx[tn][2]);
                }
            // reload B-lo into Bx, term Ah*Bl
            #pragma unroll
            for (int tn = 0; tn < 4; tn++) {
                uint32_t row = warp_n * 64 + tn * 16 + b_row_lane;
                ldsm4(sb + SOFF_BL + row * ROWB + b_chunk * 16, Bx[tn]);
            }
            #pragma unroll
            for (int tm = 0; tm < 4; tm++)
                #pragma unroll
                for (int tn = 0; tn < 4; tn++) {
                    mma16816(acc[tm][2 * tn],     Ah[tm], &Bx[tn][0]);
                    mma16816(acc[tm][2 * tn + 1], Ah[tm], &Bx[tn][2]);
                }
        }
        __syncthreads();
    }

    // ---- write accumulators to g_y (streaming stores; keep L2 for W/x) ----
    const int g = lid >> 2, t = lid & 3;
    #pragma unroll
    for (int tm = 0; tm < 4; tm++) {
        int r0 = m0 + warp_m * 64 + tm * 16 + g;
        #pragma unroll
        for (int tn = 0; tn < 8; tn++) {
            int cc = n0 + warp_n * 64 + tn * 8 + 2 * t;
            float2 v0 = make_float2(acc[tm][tn][0], acc[tm][tn][1]);
            float2 v1 = make_float2(acc[tm][tn][2], acc[tm][tn][3]);
            __stcs((float2*)(g_y + (size_t)r0 * NTOT + cc), v0);
            __stcs((float2*)(g_y + (size_t)(r0 + 8) * NTOT + cc), v1);
        }
    }
}

// ============================================================
// Epilogue kernel: bias + GroupNorm + SiLU + scale + SiLU
// One block per (row, group): 128 threads x 4 floats = 512
// ============================================================
__global__ void __launch_bounds__(128)
epilogue_kernel_19688130085476(const float* __restrict__ bias,
                               const float* __restrict__ gn_w,
                               const float* __restrict__ gn_b,
                               const float* __restrict__ mult_w,
                               float* __restrict__ out)
{
    const int blk = blockIdx.x;
    const int row = blk >> 4;      // 4096 rows
    const int g   = blk & 15;      // 16 groups
    const int tid = threadIdx.x;
    const int col = g * GSZ + tid * 4;
    const size_t idx = (size_t)row * NTOT + col;

    float4 v = __ldcs((const float4*)(g_y + idx));
    v.x += bias[col + 0];
    v.y += bias[col + 1];
    v.z += bias[col + 2];
    v.w += bias[col + 3];

    float s  = v.x + v.y + v.z + v.w;
    float ss = v.x * v.x + v.y * v.y + v.z * v.z + v.w * v.w;

    #pragma unroll
    for (int o = 16; o > 0; o >>= 1) {
        s  += __shfl_xor_sync(0xFFFFFFFFu, s, o);
        ss += __shfl_xor_sync(0xFFFFFFFFu, ss, o);
    }
    __shared__ float sh_s[4], sh_ss[4];
    const int w = tid >> 5;
    if ((tid & 31) == 0) { sh_s[w] = s; sh_ss[w] = ss; }
    __syncthreads();
    s  = sh_s[0]  + sh_s[1]  + sh_s[2]  + sh_s[3];
    ss = sh_ss[0] + sh_ss[1] + sh_ss[2] + sh_ss[3];

    const float mean = s * (1.0f / GSZ);
    const float var  = ss * (1.0f / GSZ) - mean * mean;
    const float rinv = rsqrtf(var + 1e-5f);

    float vals[4] = {v.x, v.y, v.z, v.w};
    float res[4];
    #pragma unroll
    for (int j = 0; j < 4; j++) {
        int c = col + j;
        float n  = (vals[j] - mean) * rinv * gn_w[c] + gn_b[c];
        float s1 = n / (1.0f + __expf(-n));       // SiLU
        float m  = s1 * mult_w[c];
        res[j]   = m / (1.0f + __expf(-m));       // SiLU
    }
    float4 o4 = make_float4(res[0], res[1], res[2], res[3]);
    *(float4*)(out + idx) = o4;
}

// ============================================================
// Launch
// ============================================================
extern "C" void kernel_launch(void* const* d_in, const int* in_sizes, int n_in,
                              void* d_out, int out_size)
{
    const float* x      = (const float*)d_in[0];
    const float* W      = (const float*)d_in[1];
    const float* bias   = (const float*)d_in[2];
    const float* gn_w   = (const float*)d_in[3];
    const float* gn_b   = (const float*)d_in[4];
    const float* mult_w = (const float*)d_in[5];
    float* out = (float*)d_out;

    static int attr_done = 0;
    if (!attr_done) {
        cudaFuncSetAttribute(gemm_hmma_19688130085476,
                             cudaFuncAttributeMaxDynamicSharedMemorySize, SMEM_TOTAL);
        attr_done = 1;
    }

    // resolve device symbol addresses (host API, no allocation)
    __nv_bfloat16 *pAh, *pAl, *pBh, *pBl;
    cudaGetSymbolAddress((void**)&pAh, g_Ah);
    cudaGetSymbolAddress((void**)&pAl, g_Al);
    cudaGetSymbolAddress((void**)&pBh, g_Bh);
    cudaGetSymbolAddress((void**)&pBl, g_Bl);

    // 1) split-convert x and W to bf16 hi/lo
    {
        int n4x = MTOT * KTOT / 4;   // 2,097,152
        int n4w = NTOT * KTOT / 4;   // 4,194,304
        convert_split_19688130085476<<<(n4x + 255) / 256, 256>>>(x, pAh, pAl, n4x);
        convert_split_19688130085476<<<(n4w + 255) / 256, 256>>>(W, pBh, pBl, n4w);
    }

    // 2) GEMM
    dim3 grid(NTOT / BN, MTOT / BM);  // (32, 32)
    gemm_hmma_19688130085476<<<grid, 256, SMEM_TOTAL>>>();

    // 3) epilogue
    epilogue_kernel_19688130085476<<<MTOT * NG, 128>>>(bias, gn_w, gn_b, mult_w, out);
}

// round 3
// speedup vs baseline: 1.0186x; 1.0186x over previous
#include <cuda_runtime.h>
#include <cuda_bf16.h>
#include <cstdint>

// ============================================================
// Problem constants
// ============================================================
#define MTOT 4096
#define NTOT 8192
#define KTOT 2048
#define NG   16
#define GSZ  (NTOT / NG)   // 512

// GEMM tiling
#define BM 128
#define BN 256
#define BK 32                    // bf16 K elements per stage
#define NCHUNK (KTOT / BK)       // 64
#define NSTAGE 3

// Padded smem row stride: 32 bf16 = 64B data, padded to 80B (5x16B slots;
// 5 coprime with 8 -> conflict-free ldmatrix/cp.async without swizzle)
#define ROWB 80

#define SOFF_AH 0
#define SOFF_AL (SOFF_AH + BM * ROWB)          // 10240
#define SOFF_BH (SOFF_AL + BM * ROWB)          // 20480
#define SOFF_BL (SOFF_BH + BN * ROWB)          // 40960
#define STAGE_BYTES (SOFF_BL + BN * ROWB)      // 61440
#define SMEM_TOTAL (NSTAGE * STAGE_BYTES)      // 184320

// ============================================================
// Global scratch (static __device__ allowed; no cudaMalloc)
// ============================================================
__device__ float g_y[(size_t)MTOT * NTOT];                       // 128 MB
__device__ __nv_bfloat16 g_Ah[(size_t)MTOT * KTOT];              // 16 MB
__device__ __nv_bfloat16 g_Al[(size_t)MTOT * KTOT];              // 16 MB
__device__ __nv_bfloat16 g_Bh[(size_t)NTOT * KTOT];              // 32 MB
__device__ __nv_bfloat16 g_Bl[(size_t)NTOT * KTOT];              // 32 MB

// ============================================================
// Helpers
// ============================================================
static __device__ __forceinline__ uint32_t smem_u32(const void* p) {
    uint32_t a;
    asm("{ .reg .u64 t; cvta.to.shared.u64 t, %1; cvt.u32.u64 %0, t; }" : "=r"(a) : "l"(p));
    return a;
}

static __device__ __forceinline__ void cpasync16(uint32_t dst, const void* src) {
    asm volatile("cp.async.cg.shared.global [%0], [%1], 16;" :: "r"(dst), "l"(src) : "memory");
}
#define CP_COMMIT() asm volatile("cp.async.commit_group;" ::: "memory")
#define CP_WAIT1()  asm volatile("cp.async.wait_group 1;" ::: "memory")

static __device__ __forceinline__ void ldsm4(uint32_t addr, uint32_t* r) {
    asm volatile("ldmatrix.sync.aligned.m8n8.x4.shared.b16 {%0,%1,%2,%3}, [%4];"
                 : "=r"(r[0]), "=r"(r[1]), "=r"(r[2]), "=r"(r[3]) : "r"(addr));
}

static __device__ __forceinline__ void mma16816(float* c, const uint32_t* a, const uint32_t* b) {
    asm volatile(
        "mma.sync.aligned.m16n8k16.row.col.f32.bf16.bf16.f32 "
        "{%0,%1,%2,%3}, {%4,%5,%6,%7}, {%8,%9}, {%0,%1,%2,%3};"
        : "+f"(c[0]), "+f"(c[1]), "+f"(c[2]), "+f"(c[3])
        : "r"(a[0]), "r"(a[1]), "r"(a[2]), "r"(a[3]), "r"(b[0]), "r"(b[1]));
}

// ============================================================
// Conversion kernel: fp32 -> bf16 hi + bf16 lo (2-term split)
// ============================================================
__global__ void __launch_bounds__(256)
convert_split_19688130085476(const float* __restrict__ src,
                             __nv_bfloat16* __restrict__ dh,
                             __nv_bfloat16* __restrict__ dl,
                             int n4)
{
    int i = blockIdx.x * blockDim.x + threadIdx.x;
    if (i >= n4) return;
    float4 v = __ldg((const float4*)src + i);
    float f[4] = {v.x, v.y, v.z, v.w};
    ushort4 hh, ll;
    unsigned short* hp = &hh.x;
    unsigned short* lp = &ll.x;
    #pragma unroll
    for (int j = 0; j < 4; j++) {
        __nv_bfloat16 h = __float2bfloat16(f[j]);
        __nv_bfloat16 l = __float2bfloat16(f[j] - __bfloat162float(h));
        hp[j] = __bfloat16_as_ushort(h);
        lp[j] = __bfloat16_as_ushort(l);
    }
    ((ushort4*)dh)[i] = hh;
    ((ushort4*)dl)[i] = ll;
}

// ============================================================
// GEMM kernel: y = x @ W^T  via 3-term bf16-split HMMA
//   grid (NTOT/BN, MTOT/BM) = (32, 32), 256 threads
// ============================================================
__global__ void __launch_bounds__(256)
gemm_hmma_19688130085476()
{
    extern __shared__ __align__(128) char smem[];
    const uint32_t sbase = smem_u32(smem);
    const int tid = threadIdx.x;
    const int wid = tid >> 5;
    const int lid = tid & 31;

    const int n0 = blockIdx.x * BN;
    const int m0 = blockIdx.y * BM;

    const int warp_m = wid >> 2;   // 0..1 -> 64-row slab
    const int warp_n = wid & 3;    // 0..3 -> 64-col slab

    // ldmatrix lane address components (m8n8.x4 matrix ordering)
    const int a_row_lane   = (lid & 7) + (((lid >> 3) & 1) << 3);
    const int a_chunk_lane = (lid >> 4) & 1;
    const int b_row_lane   = (lid & 7) + (((lid >> 4) & 1) << 3);
    const int b_chunk_lane = (lid >> 3) & 1;

    float acc[4][8][4];
    #pragma unroll
    for (int i = 0; i < 4; i++)
        #pragma unroll
        for (int j = 0; j < 8; j++)
            #pragma unroll
            for (int e = 0; e < 4; e++) acc[i][j][e] = 0.0f;

    // ---- stage loader ----
    auto load_stage = [&](int kc, int slot) {
        const uint32_t sb = sbase + slot * STAGE_BYTES;
        const int k0 = kc * BK;
        #pragma unroll
        for (int i = tid; i < BM * 4; i += 256) {
            int r = i >> 2, c = i & 3;
            size_t g = (size_t)(m0 + r) * KTOT + k0 + c * 8;
            uint32_t d = sb + r * ROWB + c * 16;
            cpasync16(d + SOFF_AH, g_Ah + g);
            cpasync16(d + SOFF_AL, g_Al + g);
        }
        #pragma unroll
        for (int i = tid; i < BN * 4; i += 256) {
            int r = i >> 2, c = i & 3;
            size_t g = (size_t)(n0 + r) * KTOT + k0 + c * 8;
            uint32_t d = sb + r * ROWB + c * 16;
            cpasync16(d + SOFF_BH, g_Bh + g);
            cpasync16(d + SOFF_BL, g_Bl + g);
        }
    };

    // prologue: stages 0 and 1
    load_stage(0, 0); CP_COMMIT();
    load_stage(1, 1); CP_COMMIT();

    for (int kc = 0; kc < NCHUNK; kc++) {
        CP_WAIT1();
        // Single barrier per iteration: makes stage kc visible to all warps AND
        // guarantees every warp finished reading slot (kc-1)%3 == (kc+2)%3
        // (they read it during iter kc-1, before arriving here).
        __syncthreads();

        // prefetch stage kc+2 into the slot freed at iter kc-1
        if (kc + 2 < NCHUNK) load_stage(kc + 2, (kc + 2) % NSTAGE);
        CP_COMMIT();  // exactly one commit per iteration (may be empty group)

        // ---- compute stage kc ----
        const uint32_t sb = sbase + (kc % NSTAGE) * STAGE_BYTES;
        #pragma unroll
        for (int ks = 0; ks < 2; ks++) {
            // Separate register sets for all four fragment groups: no WAR
            // hazard, all 16 ldsm issue up front, 96 MMAs fully independent.
            uint32_t Ah[4][4], Al[4][4], Bh[4][4], Bl[4][4];
            const int a_chunk = 2 * ks + a_chunk_lane;
            const int b_chunk = 2 * ks + b_chunk_lane;

            #pragma unroll
            for (int tm = 0; tm < 4; tm++) {
                uint32_t row = warp_m * 64 + tm * 16 + a_row_lane;
                uint32_t ad = sb + row * ROWB + a_chunk * 16;
                ldsm4(ad + SOFF_AH, Ah[tm]);
                ldsm4(ad + SOFF_AL, Al[tm]);
            }
            #pragma unroll
            for (int tn = 0; tn < 4; tn++) {
                uint32_t row = warp_n * 64 + tn * 16 + b_row_lane;
                uint32_t bd = sb + row * ROWB + b_chunk * 16;
                ldsm4(bd + SOFF_BH, Bh[tn]);
                ldsm4(bd + SOFF_BL, Bl[tn]);
            }

            #pragma unroll
            for (int tm = 0; tm < 4; tm++)
                #pragma unroll
                for (int tn = 0; tn < 4; tn++) {
                    mma16816(acc[tm][2 * tn],     Ah[tm], &Bh[tn][0]);
                    mma16816(acc[tm][2 * tn + 1], Ah[tm], &Bh[tn][2]);
                    mma16816(acc[tm][2 * tn],     Al[tm], &Bh[tn][0]);
                    mma16816(acc[tm][2 * tn + 1], Al[tm], &Bh[tn][2]);
                    mma16816(acc[tm][2 * tn],     Ah[tm], &Bl[tn][0]);
                    mma16816(acc[tm][2 * tn + 1], Ah[tm], &Bl[tn][2]);
                }
        }
    }

    // ---- write accumulators to g_y (streaming stores; keep L2 for W/x) ----
    const int g = lid >> 2, t = lid & 3;
    #pragma unroll
    for (int tm = 0; tm < 4; tm++) {
        int r0 = m0 + warp_m * 64 + tm * 16 + g;
        #pragma unroll
        for (int tn = 0; tn < 8; tn++) {
            int cc = n0 + warp_n * 64 + tn * 8 + 2 * t;
            float2 v0 = make_float2(acc[tm][tn][0], acc[tm][tn][1]);
            float2 v1 = make_float2(acc[tm][tn][2], acc[tm][tn][3]);
            __stcs((float2*)(g_y + (size_t)r0 * NTOT + cc), v0);
            __stcs((float2*)(g_y + (size_t)(r0 + 8) * NTOT + cc), v1);
        }
    }
}

// ============================================================
// Epilogue kernel: bias + GroupNorm + SiLU + scale + SiLU
// One block per (row, group): 128 threads x 4 floats = 512
// All parameter vectors loaded as float4 (L1-wavefront fix)
// ============================================================
__global__ void __launch_bounds__(128)
epilogue_kernel_19688130085476(const float* __restrict__ bias,
                               const float* __restrict__ gn_w,
                               const float* __restrict__ gn_b,
                               const float* __restrict__ mult_w,
                               float* __restrict__ out)
{
    const int blk = blockIdx.x;
    const int row = blk >> 4;      // 4096 rows
    const int g   = blk & 15;      // 16 groups
    const int tid = threadIdx.x;
    const int col = g * GSZ + tid * 4;
    const size_t idx = (size_t)row * NTOT + col;

    float4 v  = __ldcs((const float4*)(g_y + idx));
    float4 bb = __ldg((const float4*)(bias + col));
    v.x += bb.x; v.y += bb.y; v.z += bb.z; v.w += bb.w;

    float s  = v.x + v.y + v.z + v.w;
    float ss = v.x * v.x + v.y * v.y + v.z * v.z + v.w * v.w;

    #pragma unroll
    for (int o = 16; o > 0; o >>= 1) {
        s  += __shfl_xor_sync(0xFFFFFFFFu, s, o);
        ss += __shfl_xor_sync(0xFFFFFFFFu, ss, o);
    }
    __shared__ float sh_s[4], sh_ss[4];
    const int w = tid >> 5;
    if ((tid & 31) == 0) { sh_s[w] = s; sh_ss[w] = ss; }
    __syncthreads();
    s  = sh_s[0]  + sh_s[1]  + sh_s[2]  + sh_s[3];
    ss = sh_ss[0] + sh_ss[1] + sh_ss[2] + sh_ss[3];

    const float mean = s * (1.0f / GSZ);
    const float var  = ss * (1.0f / GSZ) - mean * mean;
    const float rinv = rsqrtf(var + 1e-5f);

    float4 gw = __ldg((const float4*)(gn_w + col));
    float4 gb = __ldg((const float4*)(gn_b + col));
    float4 mw = __ldg((const float4*)(mult_w + col));

    float vals[4] = {v.x, v.y, v.z, v.w};
    float gws[4]  = {gw.x, gw.y, gw.z, gw.w};
    float gbs[4]  = {gb.x, gb.y, gb.z, gb.w};
    float mws[4]  = {mw.x, mw.y, mw.z, mw.w};
    float res[4];
    #pragma unroll
    for (int j = 0; j < 4; j++) {
        float n  = (vals[j] - mean) * rinv * gws[j] + gbs[j];
        float s1 = n / (1.0f + __expf(-n));       // SiLU
        float m  = s1 * mws[j];
        res[j]   = m / (1.0f + __expf(-m));       // SiLU
    }
    float4 o4 = make_float4(res[0], res[1], res[2], res[3]);
    *(float4*)(out + idx) = o4;
}

// ============================================================
// Launch
// ============================================================
extern "C" void kernel_launch(void* const* d_in, const int* in_sizes, int n_in,
                              void* d_out, int out_size)
{
    const float* x      = (const float*)d_in[0];
    const float* W      = (const float*)d_in[1];
    const float* bias   = (const float*)d_in[2];
    const float* gn_w   = (const float*)d_in[3];
    const float* gn_b   = (const float*)d_in[4];
    const float* mult_w = (const float*)d_in[5];
    float* out = (float*)d_out;

    cudaFuncSetAttribute(gemm_hmma_19688130085476,
                         cudaFuncAttributeMaxDynamicSharedMemorySize, SMEM_TOTAL);

    // resolve device symbol addresses (host API, no allocation)
    __nv_bfloat16 *pAh, *pAl, *pBh, *pBl;
    cudaGetSymbolAddress((void**)&pAh, g_Ah);
    cudaGetSymbolAddress((void**)&pAl, g_Al);
    cudaGetSymbolAddress((void**)&pBh, g_Bh);
    cudaGetSymbolAddress((void**)&pBl, g_Bl);

    // 1) split-convert x and W to bf16 hi/lo
    {
        int n4x = MTOT * KTOT / 4;   // 2,097,152
        int n4w = NTOT * KTOT / 4;   // 4,194,304
        convert_split_19688130085476<<<(n4x + 255) / 256, 256>>>(x, pAh, pAl, n4x);
        convert_split_19688130085476<<<(n4w + 255) / 256, 256>>>(W, pBh, pBl, n4w);
    }

    // 2) GEMM
    dim3 grid(NTOT / BN, MTOT / BM);  // (32, 32)
    gemm_hmma_19688130085476<<<grid, 256, SMEM_TOTAL>>>();

    // 3) epilogue
    epilogue_kernel_19688130085476<<<MTOT * NG, 128>>>(bias, gn_w, gn_b, mult_w, out);
}

// round 4
// speedup vs baseline: 1.3796x; 1.3544x over previous
#include <cuda_runtime.h>
#include <cuda_bf16.h>
#include <cstdint>

// ============================================================
// Problem constants
// ============================================================
#define MTOT 4096
#define NTOT 8192
#define KTOT 2048
#define NG   16
#define GSZ  (NTOT / NG)   // 512

// GEMM tiling
#define BM 128
#define BN 256
#define BK 32                    // bf16 K elements per stage
#define NCHUNK (KTOT / BK)       // 64
#define NSTAGE 3

// Tiled+swizzled scratch layout:
//   A block (per m-tile, per k-chunk): 128 rows x 128B ([64B hi | 64B lo]) = 16KB
//   B block (per n-tile, per k-chunk): 256 rows x 128B                     = 32KB
// Rows are SW128-swizzled IN GMEM so a linear bulk copy lands swizzled in SMEM.
#define A_BLK 16384
#define B_BLK 32768
#define STAGE_BYTES (A_BLK + B_BLK)            // 49152
#define SMEM_MBAR_OFF (NSTAGE * STAGE_BYTES)   // 147456
#define SMEM_TOTAL (SMEM_MBAR_OFF + 64)        // 147520

// ============================================================
// Global scratch (static __device__ allowed; no cudaMalloc)
// ============================================================
__device__ float g_y[(size_t)MTOT * NTOT];                         // 128 MB
__device__ __align__(1024) unsigned char g_A[(size_t)MTOT * KTOT * 4];  // 32 MB (hi+lo tiled)
__device__ __align__(1024) unsigned char g_B[(size_t)NTOT * KTOT * 4];  // 64 MB (hi+lo tiled)

// ============================================================
// Helpers
// ============================================================
static __device__ __forceinline__ uint32_t smem_u32(const void* p) {
    uint32_t a;
    asm("{ .reg .u64 t; cvta.to.shared.u64 t, %1; cvt.u32.u64 %0, t; }" : "=r"(a) : "l"(p));
    return a;
}

static __device__ __forceinline__ uint32_t sw128(uint32_t off) {
    return off ^ ((off >> 3) & 0x70);
}

#define MBARRIER_INIT(addr, cnt) \
    asm volatile("mbarrier.init.shared.b64 [%0], %1;" :: "r"(addr), "r"(cnt) : "memory")

#define MBARRIER_EXPECT_TX(addr, bytes) \
    asm volatile("mbarrier.arrive.expect_tx.shared.b64 _, [%0], %1;" \
                 :: "r"(addr), "r"((uint32_t)(bytes)) : "memory")

#define MBARRIER_WAIT_PARITY(addr, par) do {                                        \
    uint32_t _m = (addr); uint32_t _p = (par); uint32_t _done;                      \
    asm volatile(                                                                    \
        "{\n\t.reg .pred p;\n\t"                                                     \
        "mbarrier.try_wait.parity.acquire.cta.shared::cta.b64 p, [%1], %2;\n\t"      \
        "selp.b32 %0, 1, 0, p;\n\t}"                                                 \
        : "=r"(_done) : "r"(_m), "r"(_p) : "memory");                                \
    if (!_done) {                                                                    \
        asm volatile(                                                                \
            "{\n\t.reg .pred P1;\n\t"                                                \
            "WL_%=:\n\t"                                                             \
            "mbarrier.try_wait.parity.acquire.cta.shared::cta.b64 P1, [%0], %1, 0x989680;\n\t" \
            "@P1 bra.uni WD_%=;\n\t"                                                 \
            "bra.uni WL_%=;\n\t"                                                     \
            "WD_%=:\n\t}"                                                            \
            :: "r"(_m), "r"(_p) : "memory");                                         \
    }                                                                                \
} while (0)

// Bulk async copy gmem -> smem, completion via mbarrier transaction bytes.
// Base-ISA (sm_90+) instruction: SASS UBLKCP.
#define BULK_G2S(dst, src, bytes, mbar) \
    asm volatile("cp.async.bulk.shared::cluster.global.mbarrier::complete_tx::bytes " \
                 "[%0], [%1], %2, [%3];" \
                 :: "r"(dst), "l"(src), "r"((uint32_t)(bytes)), "r"(mbar) : "memory")

static __device__ __forceinline__ void ldsm4(uint32_t addr, uint32_t* r) {
    asm volatile("ldmatrix.sync.aligned.m8n8.x4.shared.b16 {%0,%1,%2,%3}, [%4];"
                 : "=r"(r[0]), "=r"(r[1]), "=r"(r[2]), "=r"(r[3]) : "r"(addr));
}

static __device__ __forceinline__ void mma16816(float* c, const uint32_t* a, const uint32_t* b) {
    asm volatile(
        "mma.sync.aligned.m16n8k16.row.col.f32.bf16.bf16.f32 "
        "{%0,%1,%2,%3}, {%4,%5,%6,%7}, {%8,%9}, {%0,%1,%2,%3};"
        : "+f"(c[0]), "+f"(c[1]), "+f"(c[2]), "+f"(c[3])
        : "r"(a[0]), "r"(a[1]), "r"(a[2]), "r"(a[3]), "r"(b[0]), "r"(b[1]));
}

static __device__ __forceinline__ uint32_t pack_bf16(__nv_bfloat16 a, __nv_bfloat16 b) {
    uint32_t ua = (uint32_t)__bfloat16_as_ushort(a);
    uint32_t ub = (uint32_t)__bfloat16_as_ushort(b);
    return ua | (ub << 16);
}

// ============================================================
// Conversion kernel: fp32 -> tiled + SW128-swizzled bf16 hi/lo blocks
//   TLOG: log2(rows per tile)   (A: 7 -> 128, B: 8 -> 256)
//   Block bytes = (1 << (TLOG + 7))
// ============================================================
template <int TLOG>
__global__ void __launch_bounds__(256)
convert_tiled_19688130085476(const float* __restrict__ src,
                             unsigned char* __restrict__ dst, int n4)
{
    int i = blockIdx.x * blockDim.x + threadIdx.x;
    if (i >= n4) return;

    const int row = i >> 9;           // KTOT/4 = 512 quads per row
    const int q   = i & 511;
    const int k0  = q * 4;
    const int kc  = k0 >> 5;          // k-chunk
    const int c   = k0 & 31;          // element within chunk (multiple of 4)
    const int tile = row >> TLOG;
    const int r    = row & ((1 << TLOG) - 1);

    float4 v = __ldg((const float4*)src + i);
    float f[4] = {v.x, v.y, v.z, v.w};
    __nv_bfloat16 h[4], l[4];
    #pragma unroll
    for (int j = 0; j < 4; j++) {
        h[j] = __float2bfloat16(f[j]);
        l[j] = __float2bfloat16(f[j] - __bfloat162float(h[j]));
    }

    const size_t base = ((size_t)(tile * NCHUNK + kc)) << (TLOG + 7);
    const uint32_t off_h = (uint32_t)(r * 128 + c * 2);       // 8B-aligned
    const uint32_t off_l = off_h + 64;

    uint2 hv; hv.x = pack_bf16(h[0], h[1]); hv.y = pack_bf16(h[2], h[3]);
    uint2 lv; lv.x = pack_bf16(l[0], l[1]); lv.y = pack_bf16(l[2], l[3]);
    *(uint2*)(dst + base + sw128(off_h)) = hv;
    *(uint2*)(dst + base + sw128(off_l)) = lv;
}

// ============================================================
// GEMM kernel: y = x @ W^T  via 3-term bf16-split HMMA
//   grid (NTOT/BN, MTOT/BM) = (32, 32), 256 threads
//   Stage loads: 2 x cp.async.bulk per stage (issue cost ~0)
// ============================================================
__global__ void __launch_bounds__(256)
gemm_hmma_19688130085476()
{
    extern __shared__ __align__(1024) char smem[];
    const uint32_t sbase = smem_u32(smem);
    const uint32_t mbars = sbase + SMEM_MBAR_OFF;
    const int tid = threadIdx.x;
    const int wid = tid >> 5;
    const int lid = tid & 31;

    const int n_tile = blockIdx.x;
    const int m_tile = blockIdx.y;
    const int n0 = n_tile * BN;
    const int m0 = m_tile * BM;

    const int warp_m = wid >> 2;   // 0..1 -> 64-row slab
    const int warp_n = wid & 3;    // 0..3 -> 64-col slab

    // ldmatrix lane address components (m8n8.x4 matrix ordering)
    const int a_row_lane   = (lid & 7) + (((lid >> 3) & 1) << 3);
    const int a_chunk_lane = (lid >> 4) & 1;
    const int b_row_lane   = (lid & 7) + (((lid >> 4) & 1) << 3);
    const int b_chunk_lane = (lid >> 3) & 1;

    float acc[4][8][4];
    #pragma unroll
    for (int i = 0; i < 4; i++)
        #pragma unroll
        for (int j = 0; j < 8; j++)
            #pragma unroll
            for (int e = 0; e < 4; e++) acc[i][j][e] = 0.0f;

    if (tid == 0) {
        #pragma unroll
        for (int s = 0; s < NSTAGE; s++) MBARRIER_INIT(mbars + s * 8, 1);
    }
    __syncthreads();

    const unsigned char* Abase = g_A + ((size_t)m_tile * NCHUNK) * A_BLK;
    const unsigned char* Bbase = g_B + ((size_t)n_tile * NCHUNK) * B_BLK;

    auto produce = [&](int kc, int slot) {
        const uint32_t mb = mbars + slot * 8;
        const uint32_t sd = sbase + slot * STAGE_BYTES;
        MBARRIER_EXPECT_TX(mb, STAGE_BYTES);
        BULK_G2S(sd,         Abase + (size_t)kc * A_BLK, A_BLK, mb);
        BULK_G2S(sd + A_BLK, Bbase + (size_t)kc * B_BLK, B_BLK, mb);
    };

    if (tid == 0) { produce(0, 0); produce(1, 1); }

    for (int kc = 0; kc < NCHUNK; kc++) {
        const int slot = kc % NSTAGE;
        const uint32_t par = (uint32_t)((kc / NSTAGE) & 1);
        MBARRIER_WAIT_PARITY(mbars + slot * 8, par);
        // Barrier: everyone is past the wait AND has finished iter kc-1's
        // compute (slot (kc-1)%3 == (kc+2)%3 is therefore free to overwrite).
        __syncthreads();
        if (tid == 0 && kc + 2 < NCHUNK) produce(kc + 2, (kc + 2) % NSTAGE);

        // ---- compute stage kc ----
        const uint32_t slotA = sbase + slot * STAGE_BYTES;
        const uint32_t slotB = slotA + A_BLK;
        #pragma unroll
        for (int ks = 0; ks < 2; ks++) {
            uint32_t Ah[4][4], Al[4][4], Bh[4][4], Bl[4][4];
            const int a_chunk = 2 * ks + a_chunk_lane;
            const int b_chunk = 2 * ks + b_chunk_lane;

            #pragma unroll
            for (int tm = 0; tm < 4; tm++) {
                uint32_t row = warp_m * 64 + tm * 16 + a_row_lane;
                uint32_t off = row * 128 + a_chunk * 16;
                ldsm4(slotA + sw128(off),      Ah[tm]);
                ldsm4(slotA + sw128(off + 64), Al[tm]);
            }
            #pragma unroll
            for (int tn = 0; tn < 4; tn++) {
                uint32_t row = warp_n * 64 + tn * 16 + b_row_lane;
                uint32_t off = row * 128 + b_chunk * 16;
                ldsm4(slotB + sw128(off),      Bh[tn]);
                ldsm4(slotB + sw128(off + 64), Bl[tn]);
            }

            #pragma unroll
            for (int tm = 0; tm < 4; tm++)
                #pragma unroll
                for (int tn = 0; tn < 4; tn++) {
                    mma16816(acc[tm][2 * tn],     Ah[tm], &Bh[tn][0]);
                    mma16816(acc[tm][2 * tn + 1], Ah[tm], &Bh[tn][2]);
                    mma16816(acc[tm][2 * tn],     Al[tm], &Bh[tn][0]);
                    mma16816(acc[tm][2 * tn + 1], Al[tm], &Bh[tn][2]);
                    mma16816(acc[tm][2 * tn],     Ah[tm], &Bl[tn][0]);
                    mma16816(acc[tm][2 * tn + 1], Ah[tm], &Bl[tn][2]);
                }
        }
    }

    // ---- write accumulators to g_y (streaming stores; keep L2 for A/B) ----
    const int g = lid >> 2, t = lid & 3;
    #pragma unroll
    for (int tm = 0; tm < 4; tm++) {
        int r0 = m0 + warp_m * 64 + tm * 16 + g;
        #pragma unroll
        for (int tn = 0; tn < 8; tn++) {
            int cc = n0 + warp_n * 64 + tn * 8 + 2 * t;
            float2 v0 = make_float2(acc[tm][tn][0], acc[tm][tn][1]);
            float2 v1 = make_float2(acc[tm][tn][2], acc[tm][tn][3]);
            __stcs((float2*)(g_y + (size_t)r0 * NTOT + cc), v0);
            __stcs((float2*)(g_y + (size_t)(r0 + 8) * NTOT + cc), v1);
        }
    }
}

// ============================================================
// Epilogue kernel: bias + GroupNorm + SiLU + scale + SiLU
// One block per (row, group): 128 threads x 4 floats = 512
// ============================================================
__global__ void __launch_bounds__(128)
epilogue_kernel_19688130085476(const float* __restrict__ bias,
                               const float* __restrict__ gn_w,
                               const float* __restrict__ gn_b,
                               const float* __restrict__ mult_w,
                               float* __restrict__ out)
{
    const int blk = blockIdx.x;
    const int row = blk >> 4;      // 4096 rows
    const int g   = blk & 15;      // 16 groups
    const int tid = threadIdx.x;
    const int col = g * GSZ + tid * 4;
    const size_t idx = (size_t)row * NTOT + col;

    float4 v  = __ldcs((const float4*)(g_y + idx));
    float4 bb = __ldg((const float4*)(bias + col));
    v.x += bb.x; v.y += bb.y; v.z += bb.z; v.w += bb.w;

    float s  = v.x + v.y + v.z + v.w;
    float ss = v.x * v.x + v.y * v.y + v.z * v.z + v.w * v.w;

    #pragma unroll
    for (int o = 16; o > 0; o >>= 1) {
        s  += __shfl_xor_sync(0xFFFFFFFFu, s, o);
        ss += __shfl_xor_sync(0xFFFFFFFFu, ss, o);
    }
    __shared__ float sh_s[4], sh_ss[4];
    const int w = tid >> 5;
    if ((tid & 31) == 0) { sh_s[w] = s; sh_ss[w] = ss; }
    __syncthreads();
    s  = sh_s[0]  + sh_s[1]  + sh_s[2]  + sh_s[3];
    ss = sh_ss[0] + sh_ss[1] + sh_ss[2] + sh_ss[3];

    const float mean = s * (1.0f / GSZ);
    const float var  = ss * (1.0f / GSZ) - mean * mean;
    const float rinv = rsqrtf(var + 1e-5f);

    float4 gw = __ldg((const float4*)(gn_w + col));
    float4 gb = __ldg((const float4*)(gn_b + col));
    float4 mw = __ldg((const float4*)(mult_w + col));

    float vals[4] = {v.x, v.y, v.z, v.w};
    float gws[4]  = {gw.x, gw.y, gw.z, gw.w};
    float gbs[4]  = {gb.x, gb.y, gb.z, gb.w};
    float mws[4]  = {mw.x, mw.y, mw.z, mw.w};
    float res[4];
    #pragma unroll
    for (int j = 0; j < 4; j++) {
        float n  = (vals[j] - mean) * rinv * gws[j] + gbs[j];
        float s1 = n / (1.0f + __expf(-n));       // SiLU
        float m  = s1 * mws[j];
        res[j]   = m / (1.0f + __expf(-m));       // SiLU
    }
    float4 o4 = make_float4(res[0], res[1], res[2], res[3]);
    *(float4*)(out + idx) = o4;
}

// ============================================================
// Launch
// ============================================================
extern "C" void kernel_launch(void* const* d_in, const int* in_sizes, int n_in,
                              void* d_out, int out_size)
{
    const float* x      = (const float*)d_in[0];
    const float* W      = (const float*)d_in[1];
    const float* bias   = (const float*)d_in[2];
    const float* gn_w   = (const float*)d_in[3];
    const float* gn_b   = (const float*)d_in[4];
    const float* mult_w = (const float*)d_in[5];
    float* out = (float*)d_out;

    cudaFuncSetAttribute(gemm_hmma_19688130085476,
                         cudaFuncAttributeMaxDynamicSharedMemorySize, SMEM_TOTAL);

    unsigned char *pA, *pB;
    cudaGetSymbolAddress((void**)&pA, g_A);
    cudaGetSymbolAddress((void**)&pB, g_B);

    // 1) split-convert x and W into tiled+swizzled hi/lo blocks
    {
        int n4x = MTOT * KTOT / 4;   // 2,097,152
        int n4w = NTOT * KTOT / 4;   // 4,194,304
        convert_tiled_19688130085476<7><<<(n4x + 255) / 256, 256>>>(x, pA, n4x);
        convert_tiled_19688130085476<8><<<(n4w + 255) / 256, 256>>>(W, pB, n4w);
    }

    // 2) GEMM
    dim3 grid(NTOT / BN, MTOT / BM);  // (32, 32)
    gemm_hmma_19688130085476<<<grid, 256, SMEM_TOTAL>>>();

    // 3) epilogue
    epilogue_kernel_19688130085476<<<MTOT * NG, 128>>>(bias, gn_w, gn_b, mult_w, out);
}